// round 15
// baseline (speedup 1.0000x reference)
#include <cuda_runtime.h>
#include <math.h>

#define NN    4096
#define INS   256
#define OUTS  64
#define MECHS 4
#define LEAKF 0.2f
#define LOG2E 1.4426950408889634f
#define ADJW  (NN/32)     // 128 words per row

// ---------------- scratch (device globals; no allocation allowed) ------------
__device__ float    g_pool_part[256][256];
__device__ float    g_gb[512];                       // gamma[256], beta[256]
__device__ unsigned g_hb[MECHS * 32 * 4096];          // H bf16 MMA-B layout, 2 MB
__device__ float    g_esrc[MECHS * NN];               // prescaled by LOG2E
__device__ float    g_edst4[MECHS * 32 * 32 * 4];     // paired e_dst
__device__ unsigned g_adjbits[NN * ADJW];             // packed adjacency, 2 MB
__device__ uint2    g_wp[MECHS * 128 * 64];           // W paired-tf32, 256 KB

// ---------------- helpers ----------------------------------------------------
__device__ __forceinline__ unsigned f2tf32(float f) {
    unsigned u;
    asm("cvt.rna.tf32.f32 %0, %1;" : "=r"(u) : "f"(f));
    return u;
}

__device__ __forceinline__ unsigned bf16x2pk(float hi, float lo) {
    unsigned r;
    asm("cvt.rn.bf16x2.f32 %0, %1, %2;" : "=r"(r) : "f"(hi), "f"(lo));
    return r;
}

__device__ __forceinline__ float ex2f(float x) {
    float r;
    asm("ex2.approx.f32 %0, %1;" : "=f"(r) : "f"(x));
    return r;
}

__device__ __forceinline__ void mma_tf32(float c[4],
                                         unsigned a0, unsigned a1, unsigned a2, unsigned a3,
                                         unsigned b0, unsigned b1) {
    asm volatile(
        "mma.sync.aligned.m16n8k8.row.col.f32.tf32.tf32.f32 "
        "{%0,%1,%2,%3}, {%4,%5,%6,%7}, {%8,%9}, {%0,%1,%2,%3};"
        : "+f"(c[0]), "+f"(c[1]), "+f"(c[2]), "+f"(c[3])
        : "r"(a0), "r"(a1), "r"(a2), "r"(a3), "r"(b0), "r"(b1));
}

__device__ __forceinline__ void mma_bf16(float c[4],
                                         unsigned a0, unsigned a1, unsigned a2, unsigned a3,
                                         unsigned b0, unsigned b1) {
    asm volatile(
        "mma.sync.aligned.m16n8k16.row.col.f32.bf16.bf16.f32 "
        "{%0,%1,%2,%3}, {%4,%5,%6,%7}, {%8,%9}, {%0,%1,%2,%3};"
        : "+f"(c[0]), "+f"(c[1]), "+f"(c[2]), "+f"(c[3])
        : "r"(a0), "r"(a1), "r"(a2), "r"(a3), "r"(b0), "r"(b1));
}

__device__ __forceinline__ unsigned smaddr(const void* p) {
    return (unsigned)__cvta_generic_to_shared(p);
}

#define CPAS16(dst, src) \
    asm volatile("cp.async.cg.shared.global [%0], [%1], 16;" :: "r"(dst), "l"(src))
#define CP_COMMIT() asm volatile("cp.async.commit_group;")
#define CP_WAIT1()  asm volatile("cp.async.wait_group 1;")
#define CP_WAIT0()  asm volatile("cp.async.wait_group 0;")

// H-layout word index for (m, even row j0, col n)
__device__ __forceinline__ size_t hbword(int m, int j0, int n) {
    int jj = j0 & 15;
    int row32 = ((j0 & 127) >> 4) * 4 + ((jj & 7) >> 1);
    int half  = jj >> 3;
    return ((size_t)m * 32 + (j0 >> 7)) * 4096 + row32 * 128 + n * 2 + half;
}

__device__ __forceinline__ int edidx(int m, int row) {
    int jj = row & 15;
    return ((((int)m * 32 + (row >> 7)) * 32 +
             ((row & 127) >> 4) * 4 + ((jj & 7) >> 1)) << 2) +
           (jj & 1) + ((jj >> 3) << 1);
}

// ---------------- 1) column-mean of x ----------------------------------------
__global__ void pool_partial_k(const float* __restrict__ x) {
    int t = threadIdx.x, b = blockIdx.x;
    int r0 = b * 16;
    float acc = 0.f;
    #pragma unroll
    for (int r = 0; r < 16; ++r) acc += x[(r0 + r) * INS + t];
    g_pool_part[b][t] = acc;
}

// ---------------- 2) pool-final + conditioner (merged, 512 threads) ----------
__global__ void poolcond_k(const float* __restrict__ Wc, const float* __restrict__ bc) {
    __shared__ float ps[256];
    int t = threadIdx.x;
    if (t < 256) {
        float acc = 0.f;
        for (int b = 0; b < 256; ++b) acc += g_pool_part[b][t];
        ps[t] = acc * (1.0f / NN);
    }
    __syncthreads();
    float acc = bc[t];
    for (int i = 0; i < INS; ++i) acc = fmaf(ps[i], Wc[i * 512 + t], acc);
    g_gb[t] = acc;
}

// ---------------- 2b) W -> paired tf32 (128 blocks, 1 elem/thread) -----------
__global__ void wcvt_k(const float* __restrict__ W) {
    int idx = blockIdx.x * 256 + threadIdx.x;      // 0 .. 32767
    int m = idx >> 13, rem = idx & 8191;
    int kp = rem >> 6, n = rem & 63;
    int k = (kp >> 2) * 8 + (kp & 3);
    float w0 = W[((size_t)m * INS + k) * OUTS + n];
    float w1 = W[((size_t)m * INS + k + 4) * OUTS + n];
    g_wp[idx] = make_uint2(f2tf32(w0), f2tf32(w1));
}

// ---------------- 4) fused hgemm (blocks 0..127) + pack_adj (128..8319) ------
// hgemm: h = FiLM(x @ W[m]) via tf32 MMA + fused esd, bf16-pair H store.
// pack:  adjacency bitmask, 8 words per warp (MLP=8).
// hgemm blocks are scheduled first; pack blocks fill remaining SM slots so the
// HBM-bound pack overlaps the tensor-bound hgemm.
#define XS_WORDS (128 * 68)
#define WS_WORDS (32 * 136)
#define HG_BUF   (XS_WORDS + WS_WORDS)
#define HG_SMEM  (2 * HG_BUF * 4)
#define HG_BLOCKS (MECHS * NN / 128)     // 128
#define PK_BLOCKS (NN * ADJW / 64)       // 8192

extern __shared__ unsigned sm_u[];

__global__ void __launch_bounds__(256) hgpack_k(const float* __restrict__ x,
                                                const float* __restrict__ a1,
                                                const float* __restrict__ a2,
                                                const int* __restrict__ adj) {
    if (blockIdx.x >= HG_BLOCKS) {
        // ---- pack_adj body ----
        int pb   = blockIdx.x - HG_BLOCKS;
        int w0   = (pb * 8 + (threadIdx.x >> 5)) * 8;
        int lane = threadIdx.x & 31;
        const int* base = adj + w0 * 32;
        int v[8];
        #pragma unroll
        for (int i = 0; i < 8; ++i) v[i] = base[i * 32 + lane];
        #pragma unroll
        for (int i = 0; i < 8; ++i) {
            unsigned msk = __ballot_sync(0xffffffffu, v[i] > 0);
            if (lane == 0) g_adjbits[w0 + i] = msk;
        }
        return;
    }

    // ---- hgemm body ----
    const int t    = threadIdx.x;
    const int lane = t & 31, w = t >> 5;
    const int m    = blockIdx.x & 3;
    const int rb   = (blockIdx.x >> 2) * 128;
    const int r0   = w * 16;
    const int qrow = lane >> 2;
    const int qcol = lane & 3;
    const int row1 = r0 + qrow, row2 = row1 + 8;

    float c[8][4];
    #pragma unroll
    for (int n = 0; n < 8; ++n)
        #pragma unroll
        for (int q = 0; q < 4; ++q) c[n][q] = 0.f;

    const char* wsrc0 = (const char*)(g_wp + (size_t)m * 128 * 64);

    auto issue_chunk = [&](int kc, int b) {
        unsigned* xb = sm_u + b * HG_BUF;
        unsigned* wb = xb + XS_WORDS;
        #pragma unroll
        for (int it = 0; it < 8; ++it) {
            int f = t + 256 * it;
            int row = f >> 4, ch = f & 15;
            CPAS16(smaddr(xb + row * 68 + ch * 4),
                   x + (size_t)(rb + row) * INS + kc * 64 + ch * 4);
        }
        #pragma unroll
        for (int it = 0; it < 4; ++it) {
            int f = t + 256 * it;
            int row = f >> 5, ch = f & 31;
            CPAS16(smaddr(wb + row * 136 + ch * 4),
                   wsrc0 + ((size_t)(kc * 32 + row) * 64) * 8 + ch * 16);
        }
    };

    issue_chunk(0, 0);
    CP_COMMIT();

    for (int kc = 0; kc < 4; ++kc) {
        const int b = kc & 1;
        if (kc < 3) {
            issue_chunk(kc + 1, b ^ 1);
            CP_COMMIT();
            CP_WAIT1();
        } else {
            CP_WAIT0();
        }
        __syncthreads();

        const float*    xf = (const float*)(sm_u + b * HG_BUF);
        const unsigned* wb = sm_u + b * HG_BUF + XS_WORDS;

        #pragma unroll
        for (int ks = 0; ks < 8; ++ks) {
            int kk = 8 * ks + qcol;
            unsigned a0 = f2tf32(xf[row1 * 68 + kk]);
            unsigned a1r = f2tf32(xf[row2 * 68 + kk]);
            unsigned a2r = f2tf32(xf[row1 * 68 + kk + 4]);
            unsigned a3 = f2tf32(xf[row2 * 68 + kk + 4]);
            const unsigned* wrow = wb + (4 * ks + qcol) * 136 + qrow * 2;
            #pragma unroll
            for (int nt = 0; nt < 8; ++nt) {
                uint2 bp = *(const uint2*)(wrow + nt * 16);
                mma_tf32(c[nt], a0, a1r, a2r, a3, bp.x, bp.y);
            }
        }
        __syncthreads();
    }

    // epilogue: FiLM (exact fp32) + esd + bf16-pair H store
    float sp1 = 0.f, dp1 = 0.f, sp2 = 0.f, dp2 = 0.f;
    #pragma unroll
    for (int nt = 0; nt < 8; ++nt) {
        int cl0 = nt * 8 + 2 * qcol, cl1 = cl0 + 1;
        float g0 = g_gb[m * 64 + cl0], g1 = g_gb[m * 64 + cl1];
        float b0 = g_gb[256 + m * 64 + cl0], b1 = g_gb[256 + m * 64 + cl1];
        float h10 = fmaf(g0, c[nt][0], b0);
        float h11 = fmaf(g1, c[nt][1], b1);
        float h20 = fmaf(g0, c[nt][2], b0);
        float h21 = fmaf(g1, c[nt][3], b1);
        float av10 = __ldg(&a1[m * 64 + cl0]), av11 = __ldg(&a1[m * 64 + cl1]);
        float av20 = __ldg(&a2[m * 64 + cl0]), av21 = __ldg(&a2[m * 64 + cl1]);
        sp1 += h10 * av10 + h11 * av11;
        dp1 += h10 * av20 + h11 * av21;
        sp2 += h20 * av10 + h21 * av11;
        dp2 += h20 * av20 + h21 * av21;
        float p10 = __shfl_down_sync(0xffffffffu, h10, 4);
        float p11 = __shfl_down_sync(0xffffffffu, h11, 4);
        float p20 = __shfl_down_sync(0xffffffffu, h20, 4);
        float p21 = __shfl_down_sync(0xffffffffu, h21, 4);
        if (!(qrow & 1)) {
            int j0a = rb + row1, j0b = rb + row2;    // both even
            g_hb[hbword(m, j0a, cl0)] = bf16x2pk(p10, h10);
            g_hb[hbword(m, j0a, cl1)] = bf16x2pk(p11, h11);
            g_hb[hbword(m, j0b, cl0)] = bf16x2pk(p20, h20);
            g_hb[hbword(m, j0b, cl1)] = bf16x2pk(p21, h21);
        }
    }
    #pragma unroll
    for (int off = 1; off <= 2; off <<= 1) {
        sp1 += __shfl_xor_sync(0xffffffffu, sp1, off);
        dp1 += __shfl_xor_sync(0xffffffffu, dp1, off);
        sp2 += __shfl_xor_sync(0xffffffffu, sp2, off);
        dp2 += __shfl_xor_sync(0xffffffffu, dp2, off);
    }
    if (qcol == 0) {
        g_esrc[m * NN + rb + row1] = sp1 * LOG2E;
        g_esrc[m * NN + rb + row2] = sp2 * LOG2E;
        g_edst4[edidx(m, rb + row1)] = dp1 * LOG2E;
        g_edst4[edidx(m, rb + row2)] = dp2 * LOG2E;
    }
}

// ---------------- 5) fused attention: bf16 mma + ones-column denominator -----
#define HPW      (32 * 136)              // words per H buffer (68 uint2 rows)
#define SM_DS    (2 * HPW)
#define SM_ADJ   (2 * HPW + 2 * 128)
#define SM_TOTAL ((2 * HPW + 2 * 128 + 2 * 512) * 4)

__global__ void __launch_bounds__(256, 2) attn_k(float* __restrict__ out) {
    const int t    = threadIdx.x;
    const int lane = t & 31, w = t >> 5;
    const int m    = blockIdx.y;
    const int i0   = blockIdx.x * 128;
    const int r0   = w * 16;
    const int qrow = lane >> 2;
    const int qcol = lane & 3;
    const int row1 = r0 + qrow, row2 = row1 + 8;

    const float ss1 = g_esrc[m * NN + i0 + row1];
    const float ss2 = g_esrc[m * NN + i0 + row2];
    const unsigned bones = (qrow == 0) ? 0x3F803F80u : 0u;   // bf16x2(1,1)

    float c[9][4];
    #pragma unroll
    for (int n = 0; n < 9; ++n)
        #pragma unroll
        for (int q = 0; q < 4; ++q) c[n][q] = 0.f;

    const char* hgl = (const char*)(g_hb + (size_t)m * 32 * 4096);
    const char* dgl = (const char*)(g_edst4 + (size_t)m * 32 * 128);

    auto issue_tile = [&](int jt, int b) {
        unsigned* hb = sm_u + b * HPW;
        const char* hsrc = hgl + (size_t)jt * 16384;
        #pragma unroll
        for (int it = 0; it < 4; ++it) {
            int f = t + 256 * it;
            int row = f >> 5, ch = f & 31;
            CPAS16(smaddr(&hb[row * 136 + ch * 4]), hsrc + (size_t)f * 16);
        }
        if (t < 32)
            CPAS16(smaddr(sm_u + SM_DS + b * 128 + t * 4), dgl + jt * 512 + t * 16);
        if (t < 128)
            CPAS16(smaddr(sm_u + SM_ADJ + b * 512 + t * 4),
                   &g_adjbits[(size_t)(i0 + t) * ADJW + jt * 4]);
    };

    issue_tile(0, 0);
    CP_COMMIT();

    for (int jt = 0; jt < NN / 128; ++jt) {
        const int b = jt & 1;
        if (jt < NN / 128 - 1) {
            issue_tile(jt + 1, b ^ 1);
            CP_COMMIT();
            CP_WAIT1();
        } else {
            CP_WAIT0();
        }
        __syncthreads();

        const unsigned* hs = sm_u + b * HPW;
        const float4*   d4 = (const float4*)(sm_u + SM_DS + b * 128);
        const unsigned* aj = sm_u + SM_ADJ + b * 512;

        unsigned aw1 = 0, aw2 = 0;
        #pragma unroll
        for (int ks = 0; ks < 8; ++ks) {
            if ((ks & 1) == 0) {
                aw1 = aj[row1 * 4 + (ks >> 1)];
                aw2 = aj[row2 * 4 + (ks >> 1)];
            }
            const int pb = (ks & 1) * 16 + 2 * qcol;
            const float4 dd = d4[ks * 4 + qcol];

            float v00 = ss1 + dd.x, v01 = ss1 + dd.y, v02 = ss1 + dd.z, v03 = ss1 + dd.w;
            float v10 = ss2 + dd.x, v11 = ss2 + dd.y, v12 = ss2 + dd.z, v13 = ss2 + dd.w;
            v00 = fmaxf(v00, LEAKF * v00); v01 = fmaxf(v01, LEAKF * v01);
            v02 = fmaxf(v02, LEAKF * v02); v03 = fmaxf(v03, LEAKF * v03);
            v10 = fmaxf(v10, LEAKF * v10); v11 = fmaxf(v11, LEAKF * v11);
            v12 = fmaxf(v12, LEAKF * v12); v13 = fmaxf(v13, LEAKF * v13);
            float e00 = ex2f(v00), e01 = ex2f(v01), e02 = ex2f(v02), e03 = ex2f(v03);
            float e10 = ex2f(v10), e11 = ex2f(v11), e12 = ex2f(v12), e13 = ex2f(v13);
            e00 = ((aw1 >> pb)       & 1u) ? e00 : 0.f;
            e01 = ((aw1 >> (pb + 1)) & 1u) ? e01 : 0.f;
            e02 = ((aw1 >> (pb + 8)) & 1u) ? e02 : 0.f;
            e03 = ((aw1 >> (pb + 9)) & 1u) ? e03 : 0.f;
            e10 = ((aw2 >> pb)       & 1u) ? e10 : 0.f;
            e11 = ((aw2 >> (pb + 1)) & 1u) ? e11 : 0.f;
            e12 = ((aw2 >> (pb + 8)) & 1u) ? e12 : 0.f;
            e13 = ((aw2 >> (pb + 9)) & 1u) ? e13 : 0.f;

            unsigned a0 = bf16x2pk(e01, e00);
            unsigned a1 = bf16x2pk(e11, e10);
            unsigned a2 = bf16x2pk(e03, e02);
            unsigned a3 = bf16x2pk(e13, e12);

            const unsigned* hrow = hs + (ks * 4 + qcol) * 136 + qrow * 2;
            #pragma unroll
            for (int nt = 0; nt < 8; ++nt) {
                uint2 bp = *(const uint2*)(hrow + nt * 16);
                mma_bf16(c[nt], a0, a1, a2, a3, bp.x, bp.y);
            }
            mma_bf16(c[8], a0, a1, a2, a3, bones, bones);
        }
        __syncthreads();
    }

    float den1 = __shfl_sync(0xffffffffu, c[8][0], lane & ~3);
    float den2 = __shfl_sync(0xffffffffu, c[8][2], lane & ~3);
    float inv1 = den1 > 0.f ? 1.0f / den1 : 0.f;
    float inv2 = den2 > 0.f ? 1.0f / den2 : 0.f;

    float* ob = out + (size_t)(i0) * (MECHS * OUTS) + m * OUTS;
    #pragma unroll
    for (int nt = 0; nt < 8; ++nt) {
        int col = nt * 8 + 2 * qcol;
        float x0 = c[nt][0] * inv1, x1 = c[nt][1] * inv1;
        float y0 = c[nt][2] * inv2, y1 = c[nt][3] * inv2;
        x0 = x0 > 0.f ? x0 : expm1f(x0);
        x1 = x1 > 0.f ? x1 : expm1f(x1);
        y0 = y0 > 0.f ? y0 : expm1f(y0);
        y1 = y1 > 0.f ? y1 : expm1f(y1);
        *(float2*)&ob[(size_t)row1 * (MECHS * OUTS) + col] = make_float2(x0, x1);
        *(float2*)&ob[(size_t)row2 * (MECHS * OUTS) + col] = make_float2(y0, y1);
    }
}

// ---------------- launch ------------------------------------------------------
extern "C" void kernel_launch(void* const* d_in, const int* in_sizes, int n_in,
                              void* d_out, int out_size) {
    const float* x   = (const float*)d_in[0];
    const int*   adj = (const int*)  d_in[1];
    const float* W   = (const float*)d_in[2];
    const float* a1  = (const float*)d_in[3];
    const float* a2  = (const float*)d_in[4];
    const float* Wc  = (const float*)d_in[5];
    const float* bc  = (const float*)d_in[6];
    float* out = (float*)d_out;

    cudaFuncSetAttribute(hgpack_k, cudaFuncAttributeMaxDynamicSharedMemorySize,
                         HG_SMEM);
    cudaFuncSetAttribute(attn_k, cudaFuncAttributeMaxDynamicSharedMemorySize,
                         SM_TOTAL);

    pool_partial_k<<<256, 256>>>(x);
    poolcond_k<<<1, 512>>>(Wc, bc);
    wcvt_k<<<128, 256>>>(W);
    hgpack_k<<<HG_BLOCKS + PK_BLOCKS, 256, HG_SMEM>>>(x, a1, a2, adj);
    attn_k<<<dim3(NN / 128, MECHS), 256, SM_TOTAL>>>(out);
}

// round 16
// speedup vs baseline: 1.0906x; 1.0906x over previous
#include <cuda_runtime.h>
#include <math.h>

#define NN    4096
#define INS   256
#define OUTS  64
#define MECHS 4
#define LEAKF 0.2f
#define LOG2E 1.4426950408889634f
#define ADJW  (NN/32)     // 128 words per row

// ---------------- scratch (device globals; no allocation allowed) ------------
__device__ float    g_pool_part[256][256];
__device__ float    g_gb[512];                       // gamma[256], beta[256]
__device__ unsigned g_hb[MECHS * 32 * 4096];          // H bf16 MMA-B layout, 2 MB
__device__ float    g_esrc[MECHS * NN];               // prescaled by LOG2E
__device__ float    g_edst4[MECHS * 32 * 32 * 4];     // paired e_dst
__device__ unsigned g_adjbits[NN * ADJW];             // packed adjacency, 2 MB
__device__ uint2    g_wp[MECHS * 128 * 64];           // W paired-tf32, 256 KB

// ---------------- helpers ----------------------------------------------------
__device__ __forceinline__ unsigned f2tf32(float f) {
    unsigned u;
    asm("cvt.rna.tf32.f32 %0, %1;" : "=r"(u) : "f"(f));
    return u;
}

__device__ __forceinline__ unsigned bf16x2pk(float hi, float lo) {
    unsigned r;
    asm("cvt.rn.bf16x2.f32 %0, %1, %2;" : "=r"(r) : "f"(hi), "f"(lo));
    return r;
}

__device__ __forceinline__ float ex2f(float x) {
    float r;
    asm("ex2.approx.f32 %0, %1;" : "=f"(r) : "f"(x));
    return r;
}

__device__ __forceinline__ void mma_tf32(float c[4],
                                         unsigned a0, unsigned a1, unsigned a2, unsigned a3,
                                         unsigned b0, unsigned b1) {
    asm volatile(
        "mma.sync.aligned.m16n8k8.row.col.f32.tf32.tf32.f32 "
        "{%0,%1,%2,%3}, {%4,%5,%6,%7}, {%8,%9}, {%0,%1,%2,%3};"
        : "+f"(c[0]), "+f"(c[1]), "+f"(c[2]), "+f"(c[3])
        : "r"(a0), "r"(a1), "r"(a2), "r"(a3), "r"(b0), "r"(b1));
}

__device__ __forceinline__ void mma_bf16(float c[4],
                                         unsigned a0, unsigned a1, unsigned a2, unsigned a3,
                                         unsigned b0, unsigned b1) {
    asm volatile(
        "mma.sync.aligned.m16n8k16.row.col.f32.bf16.bf16.f32 "
        "{%0,%1,%2,%3}, {%4,%5,%6,%7}, {%8,%9}, {%0,%1,%2,%3};"
        : "+f"(c[0]), "+f"(c[1]), "+f"(c[2]), "+f"(c[3])
        : "r"(a0), "r"(a1), "r"(a2), "r"(a3), "r"(b0), "r"(b1));
}

__device__ __forceinline__ unsigned smaddr(const void* p) {
    return (unsigned)__cvta_generic_to_shared(p);
}

#define CPAS16(dst, src) \
    asm volatile("cp.async.cg.shared.global [%0], [%1], 16;" :: "r"(dst), "l"(src))
#define CP_COMMIT() asm volatile("cp.async.commit_group;")
#define CP_WAIT2()  asm volatile("cp.async.wait_group 2;")
#define CP_WAIT1()  asm volatile("cp.async.wait_group 1;")
#define CP_WAIT0()  asm volatile("cp.async.wait_group 0;")

// H-layout word index for (m, even row j0, col n)
__device__ __forceinline__ size_t hbword(int m, int j0, int n) {
    int jj = j0 & 15;
    int row32 = ((j0 & 127) >> 4) * 4 + ((jj & 7) >> 1);
    int half  = jj >> 3;
    return ((size_t)m * 32 + (j0 >> 7)) * 4096 + row32 * 128 + n * 2 + half;
}

__device__ __forceinline__ int edidx(int m, int row) {
    int jj = row & 15;
    return ((((int)m * 32 + (row >> 7)) * 32 +
             ((row & 127) >> 4) * 4 + ((jj & 7) >> 1)) << 2) +
           (jj & 1) + ((jj >> 3) << 1);
}

// ---------------- 1) fused prep: pool_partial + wcvt + pack_adj --------------
// All three bodies are smem-free, so fusing them costs no occupancy.
// Blocks 0..255: pool partials; 256..383: W->tf32; 384..8575: adjacency pack.
__global__ void prep_k(const float* __restrict__ x,
                       const float* __restrict__ W,
                       const int* __restrict__ adj) {
    int b = blockIdx.x;
    int t = threadIdx.x;
    if (b < 256) {
        int r0 = b * 16;
        float acc = 0.f;
        #pragma unroll
        for (int r = 0; r < 16; ++r) acc += x[(r0 + r) * INS + t];
        g_pool_part[b][t] = acc;
    } else if (b < 384) {
        int idx = (b - 256) * 256 + t;             // 0 .. 32767
        int m = idx >> 13, rem = idx & 8191;
        int kp = rem >> 6, n = rem & 63;
        int k = (kp >> 2) * 8 + (kp & 3);
        float w0 = W[((size_t)m * INS + k) * OUTS + n];
        float w1 = W[((size_t)m * INS + k + 4) * OUTS + n];
        g_wp[idx] = make_uint2(f2tf32(w0), f2tf32(w1));
    } else {
        int pb   = b - 384;
        int w0   = (pb * 8 + (t >> 5)) * 8;
        int lane = t & 31;
        const int* base = adj + w0 * 32;
        int v[8];
        #pragma unroll
        for (int i = 0; i < 8; ++i) v[i] = base[i * 32 + lane];
        #pragma unroll
        for (int i = 0; i < 8; ++i) {
            unsigned msk = __ballot_sync(0xffffffffu, v[i] > 0);
            if (lane == 0) g_adjbits[w0 + i] = msk;
        }
    }
}

// ---------------- 2) pool-final + conditioner (merged, 512 threads) ----------
__global__ void poolcond_k(const float* __restrict__ Wc, const float* __restrict__ bc) {
    __shared__ float ps[256];
    int t = threadIdx.x;
    if (t < 256) {
        float acc = 0.f;
        for (int b = 0; b < 256; ++b) acc += g_pool_part[b][t];
        ps[t] = acc * (1.0f / NN);
    }
    __syncthreads();
    float acc = bc[t];
    for (int i = 0; i < INS; ++i) acc = fmaf(ps[i], Wc[i * 512 + t], acc);
    g_gb[t] = acc;
}

// ---------------- 3) h = FiLM(x @ W[m]) via tf32 MMA + fused esd -------------
#define XS_WORDS (128 * 68)
#define WS_WORDS (32 * 136)
#define HG_BUF   (XS_WORDS + WS_WORDS)
#define HG_SMEM  (2 * HG_BUF * 4)

extern __shared__ unsigned sm_u[];

__global__ void __launch_bounds__(256) hgemm_k(const float* __restrict__ x,
                                               const float* __restrict__ a1,
                                               const float* __restrict__ a2) {
    const int t    = threadIdx.x;
    const int lane = t & 31, w = t >> 5;
    const int m    = blockIdx.x;
    const int rb   = blockIdx.y * 128;
    const int r0   = w * 16;
    const int qrow = lane >> 2;
    const int qcol = lane & 3;
    const int row1 = r0 + qrow, row2 = row1 + 8;

    float c[8][4];
    #pragma unroll
    for (int n = 0; n < 8; ++n)
        #pragma unroll
        for (int q = 0; q < 4; ++q) c[n][q] = 0.f;

    const char* wsrc0 = (const char*)(g_wp + (size_t)m * 128 * 64);

    auto issue_chunk = [&](int kc, int b) {
        unsigned* xb = sm_u + b * HG_BUF;
        unsigned* wb = xb + XS_WORDS;
        #pragma unroll
        for (int it = 0; it < 8; ++it) {
            int f = t + 256 * it;
            int row = f >> 4, ch = f & 15;
            CPAS16(smaddr(xb + row * 68 + ch * 4),
                   x + (size_t)(rb + row) * INS + kc * 64 + ch * 4);
        }
        #pragma unroll
        for (int it = 0; it < 4; ++it) {
            int f = t + 256 * it;
            int row = f >> 5, ch = f & 31;
            CPAS16(smaddr(wb + row * 136 + ch * 4),
                   wsrc0 + ((size_t)(kc * 32 + row) * 64) * 8 + ch * 16);
        }
    };

    issue_chunk(0, 0);
    CP_COMMIT();

    for (int kc = 0; kc < 4; ++kc) {
        const int b = kc & 1;
        if (kc < 3) {
            issue_chunk(kc + 1, b ^ 1);
            CP_COMMIT();
            CP_WAIT1();
        } else {
            CP_WAIT0();
        }
        __syncthreads();

        const float*    xf = (const float*)(sm_u + b * HG_BUF);
        const unsigned* wb = sm_u + b * HG_BUF + XS_WORDS;

        #pragma unroll
        for (int ks = 0; ks < 8; ++ks) {
            int kk = 8 * ks + qcol;
            unsigned a0 = f2tf32(xf[row1 * 68 + kk]);
            unsigned a1r = f2tf32(xf[row2 * 68 + kk]);
            unsigned a2r = f2tf32(xf[row1 * 68 + kk + 4]);
            unsigned a3 = f2tf32(xf[row2 * 68 + kk + 4]);
            const unsigned* wrow = wb + (4 * ks + qcol) * 136 + qrow * 2;
            #pragma unroll
            for (int nt = 0; nt < 8; ++nt) {
                uint2 bp = *(const uint2*)(wrow + nt * 16);
                mma_tf32(c[nt], a0, a1r, a2r, a3, bp.x, bp.y);
            }
        }
        __syncthreads();
    }

    // epilogue: FiLM (exact fp32) + esd + bf16-pair H store
    float sp1 = 0.f, dp1 = 0.f, sp2 = 0.f, dp2 = 0.f;
    #pragma unroll
    for (int nt = 0; nt < 8; ++nt) {
        int cl0 = nt * 8 + 2 * qcol, cl1 = cl0 + 1;
        float g0 = g_gb[m * 64 + cl0], g1 = g_gb[m * 64 + cl1];
        float b0 = g_gb[256 + m * 64 + cl0], b1 = g_gb[256 + m * 64 + cl1];
        float h10 = fmaf(g0, c[nt][0], b0);
        float h11 = fmaf(g1, c[nt][1], b1);
        float h20 = fmaf(g0, c[nt][2], b0);
        float h21 = fmaf(g1, c[nt][3], b1);
        float av10 = __ldg(&a1[m * 64 + cl0]), av11 = __ldg(&a1[m * 64 + cl1]);
        float av20 = __ldg(&a2[m * 64 + cl0]), av21 = __ldg(&a2[m * 64 + cl1]);
        sp1 += h10 * av10 + h11 * av11;
        dp1 += h10 * av20 + h11 * av21;
        sp2 += h20 * av10 + h21 * av11;
        dp2 += h20 * av20 + h21 * av21;
        float p10 = __shfl_down_sync(0xffffffffu, h10, 4);
        float p11 = __shfl_down_sync(0xffffffffu, h11, 4);
        float p20 = __shfl_down_sync(0xffffffffu, h20, 4);
        float p21 = __shfl_down_sync(0xffffffffu, h21, 4);
        if (!(qrow & 1)) {
            int j0a = rb + row1, j0b = rb + row2;    // both even
            g_hb[hbword(m, j0a, cl0)] = bf16x2pk(p10, h10);
            g_hb[hbword(m, j0a, cl1)] = bf16x2pk(p11, h11);
            g_hb[hbword(m, j0b, cl0)] = bf16x2pk(p20, h20);
            g_hb[hbword(m, j0b, cl1)] = bf16x2pk(p21, h21);
        }
    }
    #pragma unroll
    for (int off = 1; off <= 2; off <<= 1) {
        sp1 += __shfl_xor_sync(0xffffffffu, sp1, off);
        dp1 += __shfl_xor_sync(0xffffffffu, dp1, off);
        sp2 += __shfl_xor_sync(0xffffffffu, sp2, off);
        dp2 += __shfl_xor_sync(0xffffffffu, dp2, off);
    }
    if (qcol == 0) {
        g_esrc[m * NN + rb + row1] = sp1 * LOG2E;
        g_esrc[m * NN + rb + row2] = sp2 * LOG2E;
        g_edst4[edidx(m, rb + row1)] = dp1 * LOG2E;
        g_edst4[edidx(m, rb + row2)] = dp2 * LOG2E;
    }
}

// ---------------- 4) fused attention: bf16 mma, triple-buffered staging ------
// 3 buffers -> the buffer written by issue(jt+2) was last read at compute(jt-1),
// and all threads crossed the head barrier of iteration jt before any issue, so
// the per-tile tail barrier is removed (one __syncthreads per tile).
#define HPW      (32 * 136)              // words per H buffer (68 uint2 rows)
#define SM_DS    (3 * HPW)
#define SM_ADJ   (3 * HPW + 3 * 128)
#define SM_TOTAL ((3 * HPW + 3 * 128 + 3 * 512) * 4)

__global__ void __launch_bounds__(256, 2) attn_k(float* __restrict__ out) {
    const int t    = threadIdx.x;
    const int lane = t & 31, w = t >> 5;
    const int m    = blockIdx.y;
    const int i0   = blockIdx.x * 128;
    const int r0   = w * 16;
    const int qrow = lane >> 2;
    const int qcol = lane & 3;
    const int row1 = r0 + qrow, row2 = row1 + 8;

    const float ss1 = g_esrc[m * NN + i0 + row1];
    const float ss2 = g_esrc[m * NN + i0 + row2];
    const unsigned bones = (qrow == 0) ? 0x3F803F80u : 0u;   // bf16x2(1,1)

    float c[9][4];
    #pragma unroll
    for (int n = 0; n < 9; ++n)
        #pragma unroll
        for (int q = 0; q < 4; ++q) c[n][q] = 0.f;

    const char* hgl = (const char*)(g_hb + (size_t)m * 32 * 4096);
    const char* dgl = (const char*)(g_edst4 + (size_t)m * 32 * 128);

    auto issue_tile = [&](int jt) {
        const int b = jt % 3;
        unsigned* hb = sm_u + b * HPW;
        const char* hsrc = hgl + (size_t)jt * 16384;
        #pragma unroll
        for (int it = 0; it < 4; ++it) {
            int f = t + 256 * it;
            int row = f >> 5, ch = f & 31;
            CPAS16(smaddr(&hb[row * 136 + ch * 4]), hsrc + (size_t)f * 16);
        }
        if (t < 32)
            CPAS16(smaddr(sm_u + SM_DS + b * 128 + t * 4), dgl + jt * 512 + t * 16);
        if (t < 128)
            CPAS16(smaddr(sm_u + SM_ADJ + b * 512 + t * 4),
                   &g_adjbits[(size_t)(i0 + t) * ADJW + jt * 4]);
    };

    issue_tile(0);
    CP_COMMIT();
    issue_tile(1);
    CP_COMMIT();

    for (int jt = 0; jt < NN / 128; ++jt) {
        if (jt < NN / 128 - 2) {
            issue_tile(jt + 2);
            CP_COMMIT();
            CP_WAIT2();
        } else if (jt == NN / 128 - 2) {
            CP_WAIT1();
        } else {
            CP_WAIT0();
        }
        __syncthreads();

        const int b = jt % 3;
        const unsigned* hs = sm_u + b * HPW;
        const float4*   d4 = (const float4*)(sm_u + SM_DS + b * 128);
        const unsigned* aj = sm_u + SM_ADJ + b * 512;

        unsigned aw1 = 0, aw2 = 0;
        #pragma unroll
        for (int ks = 0; ks < 8; ++ks) {
            if ((ks & 1) == 0) {
                aw1 = aj[row1 * 4 + (ks >> 1)];
                aw2 = aj[row2 * 4 + (ks >> 1)];
            }
            const int pb = (ks & 1) * 16 + 2 * qcol;
            const float4 dd = d4[ks * 4 + qcol];

            float v00 = ss1 + dd.x, v01 = ss1 + dd.y, v02 = ss1 + dd.z, v03 = ss1 + dd.w;
            float v10 = ss2 + dd.x, v11 = ss2 + dd.y, v12 = ss2 + dd.z, v13 = ss2 + dd.w;
            v00 = fmaxf(v00, LEAKF * v00); v01 = fmaxf(v01, LEAKF * v01);
            v02 = fmaxf(v02, LEAKF * v02); v03 = fmaxf(v03, LEAKF * v03);
            v10 = fmaxf(v10, LEAKF * v10); v11 = fmaxf(v11, LEAKF * v11);
            v12 = fmaxf(v12, LEAKF * v12); v13 = fmaxf(v13, LEAKF * v13);
            float e00 = ex2f(v00), e01 = ex2f(v01), e02 = ex2f(v02), e03 = ex2f(v03);
            float e10 = ex2f(v10), e11 = ex2f(v11), e12 = ex2f(v12), e13 = ex2f(v13);
            e00 = ((aw1 >> pb)       & 1u) ? e00 : 0.f;
            e01 = ((aw1 >> (pb + 1)) & 1u) ? e01 : 0.f;
            e02 = ((aw1 >> (pb + 8)) & 1u) ? e02 : 0.f;
            e03 = ((aw1 >> (pb + 9)) & 1u) ? e03 : 0.f;
            e10 = ((aw2 >> pb)       & 1u) ? e10 : 0.f;
            e11 = ((aw2 >> (pb + 1)) & 1u) ? e11 : 0.f;
            e12 = ((aw2 >> (pb + 8)) & 1u) ? e12 : 0.f;
            e13 = ((aw2 >> (pb + 9)) & 1u) ? e13 : 0.f;

            unsigned a0 = bf16x2pk(e01, e00);
            unsigned a1 = bf16x2pk(e11, e10);
            unsigned a2 = bf16x2pk(e03, e02);
            unsigned a3 = bf16x2pk(e13, e12);

            const unsigned* hrow = hs + (ks * 4 + qcol) * 136 + qrow * 2;
            #pragma unroll
            for (int nt = 0; nt < 8; ++nt) {
                uint2 bp = *(const uint2*)(hrow + nt * 16);
                mma_bf16(c[nt], a0, a1, a2, a3, bp.x, bp.y);
            }
            mma_bf16(c[8], a0, a1, a2, a3, bones, bones);
        }
    }

    float den1 = __shfl_sync(0xffffffffu, c[8][0], lane & ~3);
    float den2 = __shfl_sync(0xffffffffu, c[8][2], lane & ~3);
    float inv1 = den1 > 0.f ? 1.0f / den1 : 0.f;
    float inv2 = den2 > 0.f ? 1.0f / den2 : 0.f;

    float* ob = out + (size_t)(i0) * (MECHS * OUTS) + m * OUTS;
    #pragma unroll
    for (int nt = 0; nt < 8; ++nt) {
        int col = nt * 8 + 2 * qcol;
        float x0 = c[nt][0] * inv1, x1 = c[nt][1] * inv1;
        float y0 = c[nt][2] * inv2, y1 = c[nt][3] * inv2;
        x0 = x0 > 0.f ? x0 : expm1f(x0);
        x1 = x1 > 0.f ? x1 : expm1f(x1);
        y0 = y0 > 0.f ? y0 : expm1f(y0);
        y1 = y1 > 0.f ? y1 : expm1f(y1);
        *(float2*)&ob[(size_t)row1 * (MECHS * OUTS) + col] = make_float2(x0, x1);
        *(float2*)&ob[(size_t)row2 * (MECHS * OUTS) + col] = make_float2(y0, y1);
    }
}

// ---------------- launch ------------------------------------------------------
extern "C" void kernel_launch(void* const* d_in, const int* in_sizes, int n_in,
                              void* d_out, int out_size) {
    const float* x   = (const float*)d_in[0];
    const int*   adj = (const int*)  d_in[1];
    const float* W   = (const float*)d_in[2];
    const float* a1  = (const float*)d_in[3];
    const float* a2  = (const float*)d_in[4];
    const float* Wc  = (const float*)d_in[5];
    const float* bc  = (const float*)d_in[6];
    float* out = (float*)d_out;

    cudaFuncSetAttribute(hgemm_k, cudaFuncAttributeMaxDynamicSharedMemorySize,
                         HG_SMEM);
    cudaFuncSetAttribute(attn_k, cudaFuncAttributeMaxDynamicSharedMemorySize,
                         SM_TOTAL);

    prep_k<<<384 + NN * ADJW / 64, 256>>>(x, W, adj);
    poolcond_k<<<1, 512>>>(Wc, bc);
    hgemm_k<<<dim3(MECHS, NN / 128), 256, HG_SMEM>>>(x, a1, a2);
    attn_k<<<dim3(NN / 128, MECHS), 256, SM_TOTAL>>>(out);
}

// round 17
// speedup vs baseline: 1.1324x; 1.0383x over previous
#include <cuda_runtime.h>
#include <math.h>

#define NN    4096
#define INS   256
#define OUTS  64
#define MECHS 4
#define LEAKF 0.2f
#define LOG2E 1.4426950408889634f
#define ADJW  (NN/32)     // 128 words per row

// ---------------- scratch (device globals; no allocation allowed) ------------
__device__ float    g_pool_part[256][256];
__device__ float    g_gb[512];                       // gamma[256], beta[256]
__device__ unsigned g_hb[MECHS * 32 * 4096];          // H bf16 MMA-B layout, 2 MB
__device__ float    g_esrc[MECHS * NN];               // prescaled by LOG2E
__device__ float    g_edst4[MECHS * 32 * 32 * 4];     // paired e_dst
__device__ unsigned g_adjbits[NN * ADJW];             // packed adjacency, 2 MB
__device__ uint2    g_wp[MECHS * 128 * 64];           // W paired-tf32, 256 KB

// ---------------- helpers ----------------------------------------------------
__device__ __forceinline__ unsigned f2tf32(float f) {
    unsigned u;
    asm("cvt.rna.tf32.f32 %0, %1;" : "=r"(u) : "f"(f));
    return u;
}

__device__ __forceinline__ unsigned bf16x2pk(float hi, float lo) {
    unsigned r;
    asm("cvt.rn.bf16x2.f32 %0, %1, %2;" : "=r"(r) : "f"(hi), "f"(lo));
    return r;
}

__device__ __forceinline__ float ex2f(float x) {
    float r;
    asm("ex2.approx.f32 %0, %1;" : "=f"(r) : "f"(x));
    return r;
}

// sign-replicate PRMT: byte i of result = msb-replicated selected byte
__device__ __forceinline__ unsigned prmt_lo(unsigned a, unsigned b) {
    unsigned r;   // bytes [1a,1a,1b,1b] sign-replicated -> lo16=bit@15(a), hi16=bit@15(b)
    asm("prmt.b32 %0, %1, %2, 0xDD99;" : "=r"(r) : "r"(a), "r"(b));
    return r;
}
__device__ __forceinline__ unsigned prmt_hi(unsigned a, unsigned b) {
    unsigned r;   // bytes [2a,2a,2b,2b] sign-replicated -> lo16=bit@23(a), hi16=bit@23(b)
    asm("prmt.b32 %0, %1, %2, 0xEEAA;" : "=r"(r) : "r"(a), "r"(b));
    return r;
}

__device__ __forceinline__ void mma_tf32(float c[4],
                                         unsigned a0, unsigned a1, unsigned a2, unsigned a3,
                                         unsigned b0, unsigned b1) {
    asm volatile(
        "mma.sync.aligned.m16n8k8.row.col.f32.tf32.tf32.f32 "
        "{%0,%1,%2,%3}, {%4,%5,%6,%7}, {%8,%9}, {%0,%1,%2,%3};"
        : "+f"(c[0]), "+f"(c[1]), "+f"(c[2]), "+f"(c[3])
        : "r"(a0), "r"(a1), "r"(a2), "r"(a3), "r"(b0), "r"(b1));
}

__device__ __forceinline__ void mma_bf16(float c[4],
                                         unsigned a0, unsigned a1, unsigned a2, unsigned a3,
                                         unsigned b0, unsigned b1) {
    asm volatile(
        "mma.sync.aligned.m16n8k16.row.col.f32.bf16.bf16.f32 "
        "{%0,%1,%2,%3}, {%4,%5,%6,%7}, {%8,%9}, {%0,%1,%2,%3};"
        : "+f"(c[0]), "+f"(c[1]), "+f"(c[2]), "+f"(c[3])
        : "r"(a0), "r"(a1), "r"(a2), "r"(a3), "r"(b0), "r"(b1));
}

__device__ __forceinline__ unsigned smaddr(const void* p) {
    return (unsigned)__cvta_generic_to_shared(p);
}

#define CPAS16(dst, src) \
    asm volatile("cp.async.cg.shared.global [%0], [%1], 16;" :: "r"(dst), "l"(src))
#define CP_COMMIT() asm volatile("cp.async.commit_group;")
#define CP_WAIT2()  asm volatile("cp.async.wait_group 2;")
#define CP_WAIT1()  asm volatile("cp.async.wait_group 1;")
#define CP_WAIT0()  asm volatile("cp.async.wait_group 0;")

// H-layout word index for (m, even row j0, col n)
__device__ __forceinline__ size_t hbword(int m, int j0, int n) {
    int jj = j0 & 15;
    int row32 = ((j0 & 127) >> 4) * 4 + ((jj & 7) >> 1);
    int half  = jj >> 3;
    return ((size_t)m * 32 + (j0 >> 7)) * 4096 + row32 * 128 + n * 2 + half;
}

__device__ __forceinline__ int edidx(int m, int row) {
    int jj = row & 15;
    return ((((int)m * 32 + (row >> 7)) * 32 +
             ((row & 127) >> 4) * 4 + ((jj & 7) >> 1)) << 2) +
           (jj & 1) + ((jj >> 3) << 1);
}

// ---------------- 1) fused prep: pool_partial + wcvt + pack_adj --------------
__global__ void prep_k(const float* __restrict__ x,
                       const float* __restrict__ W,
                       const int* __restrict__ adj) {
    int b = blockIdx.x;
    int t = threadIdx.x;
    if (b < 256) {
        int r0 = b * 16;
        float acc = 0.f;
        #pragma unroll
        for (int r = 0; r < 16; ++r) acc += x[(r0 + r) * INS + t];
        g_pool_part[b][t] = acc;
    } else if (b < 384) {
        int idx = (b - 256) * 256 + t;             // 0 .. 32767
        int m = idx >> 13, rem = idx & 8191;
        int kp = rem >> 6, n = rem & 63;
        int k = (kp >> 2) * 8 + (kp & 3);
        float w0 = W[((size_t)m * INS + k) * OUTS + n];
        float w1 = W[((size_t)m * INS + k + 4) * OUTS + n];
        g_wp[idx] = make_uint2(f2tf32(w0), f2tf32(w1));
    } else {
        int pb   = b - 384;
        int w0   = (pb * 8 + (t >> 5)) * 8;
        int lane = t & 31;
        const int* base = adj + w0 * 32;
        int v[8];
        #pragma unroll
        for (int i = 0; i < 8; ++i) v[i] = base[i * 32 + lane];
        #pragma unroll
        for (int i = 0; i < 8; ++i) {
            unsigned msk = __ballot_sync(0xffffffffu, v[i] > 0);
            if (lane == 0) g_adjbits[w0 + i] = msk;
        }
    }
}

// ---------------- 2) pool-final + conditioner (merged, 512 threads) ----------
__global__ void poolcond_k(const float* __restrict__ Wc, const float* __restrict__ bc) {
    __shared__ float ps[256];
    int t = threadIdx.x;
    if (t < 256) {
        float acc = 0.f;
        for (int b = 0; b < 256; ++b) acc += g_pool_part[b][t];
        ps[t] = acc * (1.0f / NN);
    }
    __syncthreads();
    float acc = bc[t];
    for (int i = 0; i < INS; ++i) acc = fmaf(ps[i], Wc[i * 512 + t], acc);
    g_gb[t] = acc;
}

// ---------------- 3) h = FiLM(x @ W[m]) via tf32 MMA + fused esd -------------
#define XS_WORDS (128 * 68)
#define WS_WORDS (32 * 136)
#define HG_BUF   (XS_WORDS + WS_WORDS)
#define HG_SMEM  (2 * HG_BUF * 4)

extern __shared__ unsigned sm_u[];

__global__ void __launch_bounds__(256) hgemm_k(const float* __restrict__ x,
                                               const float* __restrict__ a1,
                                               const float* __restrict__ a2) {
    const int t    = threadIdx.x;
    const int lane = t & 31, w = t >> 5;
    const int m    = blockIdx.x;
    const int rb   = blockIdx.y * 128;
    const int r0   = w * 16;
    const int qrow = lane >> 2;
    const int qcol = lane & 3;
    const int row1 = r0 + qrow, row2 = row1 + 8;

    float c[8][4];
    #pragma unroll
    for (int n = 0; n < 8; ++n)
        #pragma unroll
        for (int q = 0; q < 4; ++q) c[n][q] = 0.f;

    const char* wsrc0 = (const char*)(g_wp + (size_t)m * 128 * 64);

    auto issue_chunk = [&](int kc, int b) {
        unsigned* xb = sm_u + b * HG_BUF;
        unsigned* wb = xb + XS_WORDS;
        #pragma unroll
        for (int it = 0; it < 8; ++it) {
            int f = t + 256 * it;
            int row = f >> 4, ch = f & 15;
            CPAS16(smaddr(xb + row * 68 + ch * 4),
                   x + (size_t)(rb + row) * INS + kc * 64 + ch * 4);
        }
        #pragma unroll
        for (int it = 0; it < 4; ++it) {
            int f = t + 256 * it;
            int row = f >> 5, ch = f & 31;
            CPAS16(smaddr(wb + row * 136 + ch * 4),
                   wsrc0 + ((size_t)(kc * 32 + row) * 64) * 8 + ch * 16);
        }
    };

    issue_chunk(0, 0);
    CP_COMMIT();

    for (int kc = 0; kc < 4; ++kc) {
        const int b = kc & 1;
        if (kc < 3) {
            issue_chunk(kc + 1, b ^ 1);
            CP_COMMIT();
            CP_WAIT1();
        } else {
            CP_WAIT0();
        }
        __syncthreads();

        const float*    xf = (const float*)(sm_u + b * HG_BUF);
        const unsigned* wb = sm_u + b * HG_BUF + XS_WORDS;

        #pragma unroll
        for (int ks = 0; ks < 8; ++ks) {
            int kk = 8 * ks + qcol;
            unsigned a0 = f2tf32(xf[row1 * 68 + kk]);
            unsigned a1r = f2tf32(xf[row2 * 68 + kk]);
            unsigned a2r = f2tf32(xf[row1 * 68 + kk + 4]);
            unsigned a3 = f2tf32(xf[row2 * 68 + kk + 4]);
            const unsigned* wrow = wb + (4 * ks + qcol) * 136 + qrow * 2;
            #pragma unroll
            for (int nt = 0; nt < 8; ++nt) {
                uint2 bp = *(const uint2*)(wrow + nt * 16);
                mma_tf32(c[nt], a0, a1r, a2r, a3, bp.x, bp.y);
            }
        }
        __syncthreads();
    }

    // epilogue: FiLM (exact fp32) + esd + bf16-pair H store
    float sp1 = 0.f, dp1 = 0.f, sp2 = 0.f, dp2 = 0.f;
    #pragma unroll
    for (int nt = 0; nt < 8; ++nt) {
        int cl0 = nt * 8 + 2 * qcol, cl1 = cl0 + 1;
        float g0 = g_gb[m * 64 + cl0], g1 = g_gb[m * 64 + cl1];
        float b0 = g_gb[256 + m * 64 + cl0], b1 = g_gb[256 + m * 64 + cl1];
        float h10 = fmaf(g0, c[nt][0], b0);
        float h11 = fmaf(g1, c[nt][1], b1);
        float h20 = fmaf(g0, c[nt][2], b0);
        float h21 = fmaf(g1, c[nt][3], b1);
        float av10 = __ldg(&a1[m * 64 + cl0]), av11 = __ldg(&a1[m * 64 + cl1]);
        float av20 = __ldg(&a2[m * 64 + cl0]), av21 = __ldg(&a2[m * 64 + cl1]);
        sp1 += h10 * av10 + h11 * av11;
        dp1 += h10 * av20 + h11 * av21;
        sp2 += h20 * av10 + h21 * av11;
        dp2 += h20 * av20 + h21 * av21;
        float p10 = __shfl_down_sync(0xffffffffu, h10, 4);
        float p11 = __shfl_down_sync(0xffffffffu, h11, 4);
        float p20 = __shfl_down_sync(0xffffffffu, h20, 4);
        float p21 = __shfl_down_sync(0xffffffffu, h21, 4);
        if (!(qrow & 1)) {
            int j0a = rb + row1, j0b = rb + row2;    // both even
            g_hb[hbword(m, j0a, cl0)] = bf16x2pk(p10, h10);
            g_hb[hbword(m, j0a, cl1)] = bf16x2pk(p11, h11);
            g_hb[hbword(m, j0b, cl0)] = bf16x2pk(p20, h20);
            g_hb[hbword(m, j0b, cl1)] = bf16x2pk(p21, h21);
        }
    }
    #pragma unroll
    for (int off = 1; off <= 2; off <<= 1) {
        sp1 += __shfl_xor_sync(0xffffffffu, sp1, off);
        dp1 += __shfl_xor_sync(0xffffffffu, dp1, off);
        sp2 += __shfl_xor_sync(0xffffffffu, sp2, off);
        dp2 += __shfl_xor_sync(0xffffffffu, dp2, off);
    }
    if (qcol == 0) {
        g_esrc[m * NN + rb + row1] = sp1 * LOG2E;
        g_esrc[m * NN + rb + row2] = sp2 * LOG2E;
        g_edst4[edidx(m, rb + row1)] = dp1 * LOG2E;
        g_edst4[edidx(m, rb + row2)] = dp2 * LOG2E;
    }
}

// ---------------- 4) fused attention: bf16 mma, PRMT mask expansion ----------
// Masking now: expand adjacency bit pairs to 32-bit half-masks via two shifts +
// sign-replicating PRMT, then LOP3-AND the packed bf16x2 A-fragments. Replaces
// 8 per-element select chains (~20 ALU slots/k-step) with 12 slots. The ones-
// column MMA consumes the same masked fragments, so numerics are bit-identical.
#define HPW      (32 * 136)              // words per H buffer (68 uint2 rows)
#define SM_DS    (3 * HPW)
#define SM_ADJ   (3 * HPW + 3 * 128)
#define SM_TOTAL ((3 * HPW + 3 * 128 + 3 * 512) * 4)

__global__ void __launch_bounds__(256, 2) attn_k(float* __restrict__ out) {
    const int t    = threadIdx.x;
    const int lane = t & 31, w = t >> 5;
    const int m    = blockIdx.y;
    const int i0   = blockIdx.x * 128;
    const int r0   = w * 16;
    const int qrow = lane >> 2;
    const int qcol = lane & 3;
    const int row1 = r0 + qrow, row2 = row1 + 8;

    const float ss1 = g_esrc[m * NN + i0 + row1];
    const float ss2 = g_esrc[m * NN + i0 + row2];
    const unsigned bones = (qrow == 0) ? 0x3F803F80u : 0u;   // bf16x2(1,1)
    const int q2 = 2 * qcol;

    float c[9][4];
    #pragma unroll
    for (int n = 0; n < 9; ++n)
        #pragma unroll
        for (int q = 0; q < 4; ++q) c[n][q] = 0.f;

    const char* hgl = (const char*)(g_hb + (size_t)m * 32 * 4096);
    const char* dgl = (const char*)(g_edst4 + (size_t)m * 32 * 128);

    auto issue_tile = [&](int jt) {
        const int b = jt % 3;
        unsigned* hb = sm_u + b * HPW;
        const char* hsrc = hgl + (size_t)jt * 16384;
        #pragma unroll
        for (int it = 0; it < 4; ++it) {
            int f = t + 256 * it;
            int row = f >> 5, ch = f & 31;
            CPAS16(smaddr(&hb[row * 136 + ch * 4]), hsrc + (size_t)f * 16);
        }
        if (t < 32)
            CPAS16(smaddr(sm_u + SM_DS + b * 128 + t * 4), dgl + jt * 512 + t * 16);
        if (t < 128)
            CPAS16(smaddr(sm_u + SM_ADJ + b * 512 + t * 4),
                   &g_adjbits[(size_t)(i0 + t) * ADJW + jt * 4]);
    };

    issue_tile(0);
    CP_COMMIT();
    issue_tile(1);
    CP_COMMIT();

    for (int jt = 0; jt < NN / 128; ++jt) {
        if (jt < NN / 128 - 2) {
            issue_tile(jt + 2);
            CP_COMMIT();
            CP_WAIT2();
        } else if (jt == NN / 128 - 2) {
            CP_WAIT1();
        } else {
            CP_WAIT0();
        }
        __syncthreads();

        const int b = jt % 3;
        const unsigned* hs = sm_u + b * HPW;
        const float4*   d4 = (const float4*)(sm_u + SM_DS + b * 128);
        const unsigned* aj = sm_u + SM_ADJ + b * 512;

        unsigned aw1 = 0, aw2 = 0;
        #pragma unroll
        for (int ks = 0; ks < 8; ++ks) {
            if ((ks & 1) == 0) {
                aw1 = aj[row1 * 4 + (ks >> 1)];
                aw2 = aj[row2 * 4 + (ks >> 1)];
            }
            const float4 dd = d4[ks * 4 + qcol];

            float v00 = ss1 + dd.x, v01 = ss1 + dd.y, v02 = ss1 + dd.z, v03 = ss1 + dd.w;
            float v10 = ss2 + dd.x, v11 = ss2 + dd.y, v12 = ss2 + dd.z, v13 = ss2 + dd.w;
            v00 = fmaxf(v00, LEAKF * v00); v01 = fmaxf(v01, LEAKF * v01);
            v02 = fmaxf(v02, LEAKF * v02); v03 = fmaxf(v03, LEAKF * v03);
            v10 = fmaxf(v10, LEAKF * v10); v11 = fmaxf(v11, LEAKF * v11);
            v12 = fmaxf(v12, LEAKF * v12); v13 = fmaxf(v13, LEAKF * v13);
            float e00 = ex2f(v00), e01 = ex2f(v01), e02 = ex2f(v02), e03 = ex2f(v03);
            float e10 = ex2f(v10), e11 = ex2f(v11), e12 = ex2f(v12), e13 = ex2f(v13);

            // PRMT mask expansion: bit pb -> @15 (byte1 msb), pb+8 -> @23 (byte2 msb)
            unsigned wA1, wB1, wA2, wB2;
            if (ks & 1) {            // pb = 16 + 2*qcol: logical right shifts
                wA1 = aw1 >> (q2 + 1); wB1 = aw1 >> (q2 + 2);
                wA2 = aw2 >> (q2 + 1); wB2 = aw2 >> (q2 + 2);
            } else {                 // pb = 2*qcol: left shifts
                wA1 = aw1 << (15 - q2); wB1 = aw1 << (14 - q2);
                wA2 = aw2 << (15 - q2); wB2 = aw2 << (14 - q2);
            }
            unsigned m0 = prmt_lo(wA1, wB1);   // lo16=bit pb,   hi16=bit pb+1  (row1)
            unsigned m2 = prmt_hi(wA1, wB1);   // lo16=bit pb+8, hi16=bit pb+9  (row1)
            unsigned m1 = prmt_lo(wA2, wB2);   // (row2)
            unsigned m3 = prmt_hi(wA2, wB2);

            unsigned a0 = bf16x2pk(e01, e00) & m0;
            unsigned a1 = bf16x2pk(e11, e10) & m1;
            unsigned a2 = bf16x2pk(e03, e02) & m2;
            unsigned a3 = bf16x2pk(e13, e12) & m3;

            const unsigned* hrow = hs + (ks * 4 + qcol) * 136 + qrow * 2;
            #pragma unroll
            for (int nt = 0; nt < 8; ++nt) {
                uint2 bp = *(const uint2*)(hrow + nt * 16);
                mma_bf16(c[nt], a0, a1, a2, a3, bp.x, bp.y);
            }
            mma_bf16(c[8], a0, a1, a2, a3, bones, bones);
        }
    }

    float den1 = __shfl_sync(0xffffffffu, c[8][0], lane & ~3);
    float den2 = __shfl_sync(0xffffffffu, c[8][2], lane & ~3);
    float inv1 = den1 > 0.f ? 1.0f / den1 : 0.f;
    float inv2 = den2 > 0.f ? 1.0f / den2 : 0.f;

    float* ob = out + (size_t)(i0) * (MECHS * OUTS) + m * OUTS;
    #pragma unroll
    for (int nt = 0; nt < 8; ++nt) {
        int col = nt * 8 + 2 * qcol;
        float x0 = c[nt][0] * inv1, x1 = c[nt][1] * inv1;
        float y0 = c[nt][2] * inv2, y1 = c[nt][3] * inv2;
        x0 = x0 > 0.f ? x0 : expm1f(x0);
        x1 = x1 > 0.f ? x1 : expm1f(x1);
        y0 = y0 > 0.f ? y0 : expm1f(y0);
        y1 = y1 > 0.f ? y1 : expm1f(y1);
        *(float2*)&ob[(size_t)row1 * (MECHS * OUTS) + col] = make_float2(x0, x1);
        *(float2*)&ob[(size_t)row2 * (MECHS * OUTS) + col] = make_float2(y0, y1);
    }
}

// ---------------- launch ------------------------------------------------------
extern "C" void kernel_launch(void* const* d_in, const int* in_sizes, int n_in,
                              void* d_out, int out_size) {
    const float* x   = (const float*)d_in[0];
    const int*   adj = (const int*)  d_in[1];
    const float* W   = (const float*)d_in[2];
    const float* a1  = (const float*)d_in[3];
    const float* a2  = (const float*)d_in[4];
    const float* Wc  = (const float*)d_in[5];
    const float* bc  = (const float*)d_in[6];
    float* out = (float*)d_out;

    cudaFuncSetAttribute(hgemm_k, cudaFuncAttributeMaxDynamicSharedMemorySize,
                         HG_SMEM);
    cudaFuncSetAttribute(attn_k, cudaFuncAttributeMaxDynamicSharedMemorySize,
                         SM_TOTAL);

    prep_k<<<384 + NN * ADJW / 64, 256>>>(x, W, adj);
    poolcond_k<<<1, 512>>>(Wc, bc);
    hgemm_k<<<dim3(MECHS, NN / 128), 256, HG_SMEM>>>(x, a1, a2);
    attn_k<<<dim3(NN / 128, MECHS), 256, SM_TOTAL>>>(out);
}